// round 3
// baseline (speedup 1.0000x reference)
#include <cuda_runtime.h>
#include <cuda_bf16.h>
#include <math.h>

// Problem constants
#define BATCH 64
#define T 320
#define D 768
#define WD 32
#define BW 81           // max(T1,T2)//4 + 1

#define NROWS (2*BATCH*T)          // 40960 projected rows (x then y)
#define ALIGNED_ELEMS ((size_t)BATCH*T*D)
#define PATH_ELEMS    ((size_t)BATCH*T*T)

// Scratch (static device globals: allocation-free)
__device__ float g_xw[BATCH*T*WD];
__device__ float g_yw[BATCH*T*WD];
__device__ float g_colsum[BATCH*T];

// ---------------------------------------------------------------------------
// Kernel 1: projection as a tiled GEMM.
// out[r, wd] = (sum_c src[r,c] * W[wd,c] + b[wd]) * scale[wd] + shift[wd]
// CTA: 64 rows x 32 outputs, K=768 chunked by 64. Each x/y row is read from
// HBM exactly once.
// ---------------------------------------------------------------------------
#define PJ_ROWS 64
#define PJ_KC 64
#define PJ_THREADS 256
#define WS_STRIDE 33

__global__ void proj_kernel(const float* __restrict__ x, const float* __restrict__ y,
                            const float* __restrict__ W, const float* __restrict__ bias,
                            const float* __restrict__ wsc, const float* __restrict__ wsh) {
    __shared__ float xs[PJ_ROWS][PJ_KC];        // [row][k]
    __shared__ float ws[PJ_KC][WS_STRIDE];      // [k][wd] padded

    int tid = threadIdx.x;
    int wd   = tid & 31;        // output column (lane)
    int rgrp = tid >> 5;        // 0..7, 8 rows each

    int row0 = blockIdx.x * PJ_ROWS;            // 640 CTAs
    bool is_x = (row0 < BATCH*T);
    const float* src = is_x ? (x + (size_t)row0 * D)
                            : (y + (size_t)(row0 - BATCH*T) * D);

    float acc[8];
    #pragma unroll
    for (int r = 0; r < 8; r++) acc[r] = 0.f;

    for (int k0 = 0; k0 < D; k0 += PJ_KC) {
        // load x tile: 64 rows x 64 cols = 1024 float4, 4 per thread
        #pragma unroll
        for (int v = 0; v < 4; v++) {
            int idx = tid + v * PJ_THREADS;     // 0..1023 float4 index
            int r = idx >> 4;                   // 16 float4 per row
            int c4 = idx & 15;
            float4 val = *(const float4*)(src + (size_t)r * D + k0 + c4 * 4);
            *(float4*)&xs[r][c4 * 4] = val;
        }
        // load W tile transposed: ws[kc][wd] = W[wd][k0+kc]; 2048 elems, 8/thread
        #pragma unroll
        for (int v = 0; v < 8; v++) {
            int idx = tid + v * PJ_THREADS;     // 0..2047
            int w = idx >> 6;                   // wd  0..31
            int kc = idx & 63;
            ws[kc][w] = W[(size_t)w * D + k0 + kc];
        }
        __syncthreads();
        #pragma unroll
        for (int kc = 0; kc < PJ_KC; kc++) {
            float wv = ws[kc][wd];
            #pragma unroll
            for (int r = 0; r < 8; r++)
                acc[r] = fmaf(xs[rgrp * 8 + r][kc], wv, acc[r]);
        }
        __syncthreads();
    }

    float bv = bias[wd], sc = wsc[wd], sh = wsh[wd];
    float* dst = is_x ? (g_xw + (size_t)row0 * WD)
                      : (g_yw + (size_t)(row0 - BATCH*T) * WD);
    #pragma unroll
    for (int r = 0; r < 8; r++) {
        int row = rgrp * 8 + r;
        dst[(size_t)row * WD + wd] = fmaf(acc[r] + bv, sc, sh);
    }
}

// ---------------------------------------------------------------------------
// Kernel 2: banded soft-DTW DP, anti-diagonal wavefront. One CTA per batch.
// xw/yw staged in shared (rows padded to 33 floats -> conflict-free).
// Out-of-band cells are 0 and ARE read by in-band neighbors (faithful to ref).
// Writes raw DP values (band cells only) into the path region of d_out.
// ---------------------------------------------------------------------------
#define DP_THREADS 128
#define SXW_STRIDE 33
#define BUFSZ 324
#define DP_SMEM_FLOATS (2*T*SXW_STRIDE + 2*T + 3*BUFSZ)
#define DP_SMEM_BYTES (DP_SMEM_FLOATS * 4)

__global__ void dp_kernel(float* __restrict__ path) {
    int b = blockIdx.x;
    extern __shared__ float sm[];
    float* sxw = sm;                       // T*33
    float* syw = sxw + T*SXW_STRIDE;       // T*33
    float* nx  = syw + T*SXW_STRIDE;       // T
    float* ny  = nx + T;                   // T
    float* buf = ny + T;                   // 3*BUFSZ (contiguous)

    const float* gx = g_xw + (size_t)b * T * WD;
    const float* gy = g_yw + (size_t)b * T * WD;
    int tid = threadIdx.x;

    for (int idx = tid; idx < T*WD; idx += DP_THREADS) {
        int i = idx >> 5, c = idx & 31;
        sxw[i*SXW_STRIDE + c] = gx[idx];
        syw[i*SXW_STRIDE + c] = gy[idx];
    }
    for (int idx = tid; idx < 3*BUFSZ; idx += DP_THREADS) buf[idx] = 0.f;
    __syncthreads();
    for (int i = tid; i < T; i += DP_THREADS) {
        float sx = 0.f, sy = 0.f;
        #pragma unroll
        for (int c = 0; c < WD; c++) {
            float a = sxw[i*SXW_STRIDE + c]; sx = fmaf(a, a, sx);
            float d = syw[i*SXW_STRIDE + c]; sy = fmaf(d, d, sy);
        }
        nx[i] = sx; ny[i] = sy;
    }
    __syncthreads();

    float* prev2 = buf;            // diag k-2 (cell i stored at slot i+1)
    float* prev1 = buf + BUFSZ;    // diag k-1
    float* cur   = buf + 2*BUFSZ;  // diag k
    float* dp = path + (size_t)b * T * T;

    for (int k = 0; k < 2*T - 1; ++k) {
        int lo_full = max(0, k - (T-1));
        int hi_full = min(T-1, k);
        // band: j-i in [-BW, BW-1]  ->  i in [ceil((k-BW+1)/2), floor((k+BW)/2)]
        int lo_b = (k >= BW-2) ? ((k - (BW-2)) >> 1) : 0;
        if (lo_b < lo_full) lo_b = lo_full;
        int hi_b = (k + BW) >> 1;
        if (hi_b > hi_full) hi_b = hi_full;
        int lo_l = max(lo_full, lo_b - 2);   // +-2 halo: keeps zeros fresh for
        int hi_l = min(hi_full, hi_b + 2);   // neighbor reads as band shifts

        for (int i = lo_l + tid; i <= hi_l; i += DP_THREADS) {
            int j = k - i;
            int dji = j - i;
            bool inb = (dji >= -BW) && (dji <= BW - 1);
            float v = 0.0f;
            if (inb) {
                const float* xr = sxw + i*SXW_STRIDE;
                const float* yr = syw + j*SXW_STRIDE;
                float a0 = 0.f, a1 = 0.f, a2 = 0.f, a3 = 0.f;
                #pragma unroll
                for (int c = 0; c < WD; c += 4) {
                    a0 = fmaf(xr[c+0], yr[c+0], a0);
                    a1 = fmaf(xr[c+1], yr[c+1], a1);
                    a2 = fmaf(xr[c+2], yr[c+2], a2);
                    a3 = fmaf(xr[c+3], yr[c+3], a3);
                }
                float dot = (a0 + a1) + (a2 + a3);
                float dval = nx[i] + ny[j] - 2.0f * dot;
                if (i == 0 && j == 0) {
                    v = dval;
                } else {
                    float up = prev1[i];       // cell (i-1, j)
                    float lf = prev1[i + 1];   // cell (i, j-1)
                    float dg = prev2[i];       // cell (i-1, j-1)
                    bool vu = (i > 0), vl = (j > 0), vd = (i > 0) && (j > 0);
                    float m = -3.4e38f;
                    if (vd) m = fmaxf(m, -dg);
                    if (vu) m = fmaxf(m, -up);
                    if (vl) m = fmaxf(m, -lf);
                    float s = 0.f;
                    if (vd) s += expf(-dg - m);
                    if (vu) s += expf(-up - m);
                    if (vl) s += expf(-lf - m);
                    v = dval - m - logf(s);    // d + softmin (max-subtracted LSE)
                }
                dp[(size_t)i * T + j] = v;
            }
            cur[i + 1] = v;
        }
        __syncthreads();
        float* t0 = prev2; prev2 = prev1; prev1 = cur; cur = t0;
    }
}

// ---------------------------------------------------------------------------
// Kernel 3: in-place row softmax of -DP (out-of-band treated as value 0).
// One CTA per (b, t1) row. Never reads out-of-band (poisoned) cells.
// ---------------------------------------------------------------------------
__global__ void softmax_kernel(float* __restrict__ path) {
    int row = blockIdx.x;                  // b*T + t1
    int t1 = row % T;
    float* p = path + (size_t)row * T;
    __shared__ float zsh[T];
    __shared__ float red[8];
    int tid = threadIdx.x;                 // 256
    int jlo = t1 - BW, jhi = t1 + BW - 1;

    float lm = -3.4e38f;
    for (int j = tid; j < T; j += 256) {
        float v = (j >= jlo && j <= jhi) ? p[j] : 0.0f;
        float z = -v;
        zsh[j] = z;
        lm = fmaxf(lm, z);
    }
    #pragma unroll
    for (int o = 16; o; o >>= 1) lm = fmaxf(lm, __shfl_xor_sync(0xFFFFFFFFu, lm, o));
    if ((tid & 31) == 0) red[tid >> 5] = lm;
    __syncthreads();
    float m = -3.4e38f;
    #pragma unroll
    for (int w = 0; w < 8; w++) m = fmaxf(m, red[w]);
    __syncthreads();

    float ls = 0.f;
    for (int j = tid; j < T; j += 256) {
        float e = expf(zsh[j] - m);
        zsh[j] = e;
        ls += e;
    }
    #pragma unroll
    for (int o = 16; o; o >>= 1) ls += __shfl_xor_sync(0xFFFFFFFFu, ls, o);
    if ((tid & 31) == 0) red[tid >> 5] = ls;
    __syncthreads();
    float s = 0.f;
    #pragma unroll
    for (int w = 0; w < 8; w++) s += red[w];
    float inv = 1.0f / s;
    for (int j = tid; j < T; j += 256) p[j] = zsh[j] * inv;
}

// ---------------------------------------------------------------------------
// Kernel 4: column sums over t1:  colsum[b,s] = sum_t path[b,t,s] + 1e-10
// ---------------------------------------------------------------------------
__global__ void colsum_kernel(const float* __restrict__ path) {
    int idx = blockIdx.x * blockDim.x + threadIdx.x;
    if (idx >= BATCH * T) return;
    int b = idx / T, s = idx % T;
    const float* p = path + (size_t)b * T * T + s;
    float acc = 1e-10f;
    #pragma unroll 4
    for (int t = 0; t < T; ++t) acc += p[(size_t)t * T];
    g_colsum[idx] = acc;
}

// ---------------------------------------------------------------------------
// Kernel 5: aligned[b,s,d] = (sum_t path[b,t,s] * x[b,t,d]) / colsum[b,s]
// Batched fp32 GEMM, 64x128x32 tiles, 4x8 register blocking (FFMA-bound).
// BK=32 halves barrier count vs BK=16.
// ---------------------------------------------------------------------------
#define BM 64
#define BN 128
#define BK 32

__global__ void aligned_gemm(const float* __restrict__ path, const float* __restrict__ x,
                             float* __restrict__ out) {
    int b  = blockIdx.z;
    int s0 = blockIdx.y * BM;
    int d0 = blockIdx.x * BN;
    const float* P = path + (size_t)b * T * T;
    const float* X = x    + (size_t)b * T * D;
    float*       O = out  + (size_t)b * T * D;

    __shared__ float As[BK][BM];   // [t][s]  (P^T tile) 8KB
    __shared__ float Bs[BK][BN];   // [t][d]            16KB

    int tid = threadIdx.x;         // 256
    int tx = tid & 15;             // d-group: 16 groups x 8
    int ty = tid >> 4;             // s-group: 16 groups x 4
    float acc[4][8] = {};

    for (int t0 = 0; t0 < T; t0 += BK) {
        // As: 32x64 = 512 float4 -> 2 per thread
        #pragma unroll
        for (int v = 0; v < 2; v++) {
            int idx = tid + v * 256;       // float4 index, 16 per row
            int t = idx >> 4, c4 = idx & 15;
            *(float4*)&As[t][c4 * 4] =
                *(const float4*)(P + (size_t)(t0 + t) * T + s0 + c4 * 4);
        }
        // Bs: 32x128 = 1024 float4 -> 4 per thread
        #pragma unroll
        for (int v = 0; v < 4; v++) {
            int idx = tid + v * 256;       // float4 index, 32 per row
            int t = idx >> 5, c4 = idx & 31;
            *(float4*)&Bs[t][c4 * 4] =
                *(const float4*)(X + (size_t)(t0 + t) * D + d0 + c4 * 4);
        }
        __syncthreads();
        #pragma unroll
        for (int t = 0; t < BK; ++t) {
            float4 a  = *(const float4*)&As[t][ty * 4];
            float4 b0 = *(const float4*)&Bs[t][tx * 8];
            float4 b1 = *(const float4*)&Bs[t][tx * 8 + 4];
            float av[4] = {a.x, a.y, a.z, a.w};
            float bv[8] = {b0.x, b0.y, b0.z, b0.w, b1.x, b1.y, b1.z, b1.w};
            #pragma unroll
            for (int r = 0; r < 4; ++r)
                #pragma unroll
                for (int c = 0; c < 8; ++c)
                    acc[r][c] = fmaf(av[r], bv[c], acc[r][c]);
        }
        __syncthreads();
    }

    #pragma unroll
    for (int r = 0; r < 4; ++r) {
        int s = s0 + ty * 4 + r;
        float inv = 1.0f / g_colsum[b * T + s];
        float4 o0, o1;
        o0.x = acc[r][0]*inv; o0.y = acc[r][1]*inv; o0.z = acc[r][2]*inv; o0.w = acc[r][3]*inv;
        o1.x = acc[r][4]*inv; o1.y = acc[r][5]*inv; o1.z = acc[r][6]*inv; o1.w = acc[r][7]*inv;
        *(float4*)(O + (size_t)s * D + d0 + tx * 8)     = o0;
        *(float4*)(O + (size_t)s * D + d0 + tx * 8 + 4) = o1;
    }
}

// ---------------------------------------------------------------------------
extern "C" void kernel_launch(void* const* d_in, const int* in_sizes, int n_in,
                              void* d_out, int out_size) {
    const float* x   = (const float*)d_in[0];
    const float* y   = (const float*)d_in[1];
    const float* W   = (const float*)d_in[2];
    const float* bb  = (const float*)d_in[3];
    const float* wsc = (const float*)d_in[4];
    const float* wsh = (const float*)d_in[5];

    float* aligned = (float*)d_out;                        // [B,T,D]
    float* path    = (float*)d_out + ALIGNED_ELEMS;        // [B,T,T]

    // 1. projection (640 CTAs: x rows 0..20479, y rows 20480..40959)
    proj_kernel<<<NROWS / PJ_ROWS, PJ_THREADS>>>(x, y, W, bb, wsc, wsh);

    // 2. wavefront DP (needs >48KB dynamic smem)
    cudaFuncSetAttribute(dp_kernel, cudaFuncAttributeMaxDynamicSharedMemorySize,
                         DP_SMEM_BYTES);
    dp_kernel<<<BATCH, DP_THREADS, DP_SMEM_BYTES>>>(path);

    // 3. row softmax (in place)
    softmax_kernel<<<BATCH * T, 256>>>(path);

    // 4. column sums
    colsum_kernel<<<(BATCH * T + 255) / 256, 256>>>(path);

    // 5. aligned output
    dim3 g(D / BN, T / BM, BATCH);
    aligned_gemm<<<g, 256>>>(path, x, aligned);
}

// round 4
// speedup vs baseline: 1.1665x; 1.1665x over previous
#include <cuda_runtime.h>
#include <cuda_bf16.h>
#include <math.h>

// Problem constants
#define BATCH 64
#define T 320
#define D 768
#define WD 32
#define BW 81           // max(T1,T2)//4 + 1

#define NROWS (2*BATCH*T)          // 40960 projected rows (x then y)
#define ALIGNED_ELEMS ((size_t)BATCH*T*D)

// Scratch (static device globals: allocation-free)
__device__ float g_xw[BATCH*T*WD];
__device__ float g_yw[BATCH*T*WD];
__device__ float g_nx[BATCH*T];
__device__ float g_ny[BATCH*T];
__device__ float g_colsum[BATCH*T];
__device__ float g_dist[(size_t)BATCH*T*T];   // banded distance matrix (L2-resident)

// ---------------------------------------------------------------------------
// cp.async helpers (sm_103a: LDGSTS)
// ---------------------------------------------------------------------------
__device__ __forceinline__ void cp16(void* s, const void* g) {
    unsigned sa = (unsigned)__cvta_generic_to_shared(s);
    asm volatile("cp.async.cg.shared.global [%0], [%1], 16;" :: "r"(sa), "l"(g));
}
#define CP_COMMIT() asm volatile("cp.async.commit_group;" ::: "memory")
#define CP_WAIT(n)  asm volatile("cp.async.wait_group %0;" :: "n"(n) : "memory")

// ---------------------------------------------------------------------------
// Kernel 1: projection as a tiled GEMM + row norms.
// out[r, wd] = (sum_c src[r,c] * W[wd,c] + b[wd]) * scale[wd] + shift[wd]
// Each warp owns 8 rows fully (wd = lane), so the row norm is a lane reduce.
// ---------------------------------------------------------------------------
#define PJ_ROWS 64
#define PJ_KC 64
#define PJ_THREADS 256
#define WS_STRIDE 33

__global__ void proj_kernel(const float* __restrict__ x, const float* __restrict__ y,
                            const float* __restrict__ W, const float* __restrict__ bias,
                            const float* __restrict__ wsc, const float* __restrict__ wsh) {
    __shared__ float xs[PJ_ROWS][PJ_KC];        // [row][k]
    __shared__ float ws[PJ_KC][WS_STRIDE];      // [k][wd] padded

    int tid = threadIdx.x;
    int wd   = tid & 31;        // output column (lane)
    int rgrp = tid >> 5;        // warp id: 8 rows each

    int row0 = blockIdx.x * PJ_ROWS;            // 640 CTAs
    bool is_x = (row0 < BATCH*T);
    const float* src = is_x ? (x + (size_t)row0 * D)
                            : (y + (size_t)(row0 - BATCH*T) * D);

    float acc[8];
    #pragma unroll
    for (int r = 0; r < 8; r++) acc[r] = 0.f;

    for (int k0 = 0; k0 < D; k0 += PJ_KC) {
        #pragma unroll
        for (int v = 0; v < 4; v++) {
            int idx = tid + v * PJ_THREADS;     // float4 index
            int r = idx >> 4;
            int c4 = idx & 15;
            float4 val = *(const float4*)(src + (size_t)r * D + k0 + c4 * 4);
            *(float4*)&xs[r][c4 * 4] = val;
        }
        #pragma unroll
        for (int v = 0; v < 8; v++) {
            int idx = tid + v * PJ_THREADS;
            int w = idx >> 6;
            int kc = idx & 63;
            ws[kc][w] = W[(size_t)w * D + k0 + kc];
        }
        __syncthreads();
        #pragma unroll
        for (int kc = 0; kc < PJ_KC; kc++) {
            float wv = ws[kc][wd];
            #pragma unroll
            for (int r = 0; r < 8; r++)
                acc[r] = fmaf(xs[rgrp * 8 + r][kc], wv, acc[r]);
        }
        __syncthreads();
    }

    float bv = bias[wd], sc = wsc[wd], sh = wsh[wd];
    float* dst = is_x ? (g_xw + (size_t)row0 * WD)
                      : (g_yw + (size_t)(row0 - BATCH*T) * WD);
    float* ndst = is_x ? (g_nx + row0) : (g_ny + (row0 - BATCH*T));
    #pragma unroll
    for (int r = 0; r < 8; r++) {
        int row = rgrp * 8 + r;
        float v = fmaf(acc[r] + bv, sc, sh);
        dst[(size_t)row * WD + wd] = v;
        float sq = v * v;
        #pragma unroll
        for (int o = 16; o; o >>= 1) sq += __shfl_xor_sync(0xFFFFFFFFu, sq, o);
        if (wd == 0) ndst[row] = sq;
    }
}

// ---------------------------------------------------------------------------
// Kernel 2a: banded distance matrix. dist[b,i,j] = |xw_i|^2+|yw_j|^2-2<xw_i,yw_j>
// CTA: one batch x 16-row block; loops j tiles of 16 across the band.
// Fully parallel: hoists the 32-FMA dot out of the serial wavefront.
// ---------------------------------------------------------------------------
#define DI 16

__global__ void dist_kernel() {
    int b  = blockIdx.y;
    int i0 = blockIdx.x * DI;
    __shared__ float xs[DI][33];
    __shared__ float ys[DI][33];
    __shared__ float nxs[DI], nys[DI];

    int tid = threadIdx.x;     // 256
    const float* gx = g_xw + ((size_t)b * T + i0) * WD;
    for (int idx = tid; idx < DI * WD; idx += 256)
        xs[idx >> 5][idx & 31] = gx[idx];
    if (tid < DI) nxs[tid] = g_nx[b * T + i0 + tid];

    int jlo = max(0, i0 - BW);
    int jhi = min(T - 1, i0 + DI - 1 + BW - 1);
    int il = tid >> 4, jl = tid & 15;
    float* drow = g_dist + ((size_t)b * T + i0 + il) * T;

    for (int j0 = jlo; j0 <= jhi; j0 += DI) {
        __syncthreads();   // protects previous ys use (and first xs use)
        for (int idx = tid; idx < DI * WD; idx += 256) {
            int r = idx >> 5;
            if (j0 + r < T)
                ys[r][idx & 31] = g_yw[((size_t)b * T + j0 + r) * WD + (idx & 31)];
        }
        if (tid < DI && j0 + tid < T) nys[tid] = g_ny[b * T + j0 + tid];
        __syncthreads();

        int i = i0 + il, j = j0 + jl;
        if (j < T && j >= i - BW && j <= i + BW - 1) {
            float a0 = 0.f, a1 = 0.f, a2 = 0.f, a3 = 0.f;
            #pragma unroll
            for (int c = 0; c < WD; c += 4) {
                a0 = fmaf(xs[il][c+0], ys[jl][c+0], a0);
                a1 = fmaf(xs[il][c+1], ys[jl][c+1], a1);
                a2 = fmaf(xs[il][c+2], ys[jl][c+2], a2);
                a3 = fmaf(xs[il][c+3], ys[jl][c+3], a3);
            }
            float dot = (a0 + a1) + (a2 + a3);
            drow[j] = nxs[il] + nys[jl] - 2.0f * dot;
        }
    }
}

// ---------------------------------------------------------------------------
// Kernel 2b: banded soft-DTW DP, anti-diagonal wavefront. One CTA per batch.
// Reads precomputed dist with a one-diagonal software prefetch (L2-resident).
// Band/halo logic identical to the verified R3 version.
// ---------------------------------------------------------------------------
#define DP_THREADS 96
#define BUFSZ 324

__device__ __forceinline__ void dp_ranges(int k, int& lo_l, int& hi_l) {
    int lo_full = max(0, k - (T - 1));
    int hi_full = min(T - 1, k);
    int lo_b = (k >= BW - 2) ? ((k - (BW - 2)) >> 1) : 0;
    if (lo_b < lo_full) lo_b = lo_full;
    int hi_b = (k + BW) >> 1;
    if (hi_b > hi_full) hi_b = hi_full;
    lo_l = max(lo_full, lo_b - 2);   // +-2 halo keeps zeros fresh as band shifts
    hi_l = min(hi_full, hi_b + 2);
}

__global__ void dp_kernel(float* __restrict__ path) {
    int b = blockIdx.x;
    __shared__ float buf[3 * BUFSZ];
    int tid = threadIdx.x;
    for (int idx = tid; idx < 3 * BUFSZ; idx += DP_THREADS) buf[idx] = 0.f;
    __syncthreads();

    float* prev2 = buf;            // diag k-2 (cell i stored at slot i+1)
    float* prev1 = buf + BUFSZ;    // diag k-1
    float* cur   = buf + 2 * BUFSZ;
    float* dp = path + (size_t)b * T * T;
    const float* dist = g_dist + (size_t)b * T * T;

    int lo_l, hi_l;
    dp_ranges(0, lo_l, hi_l);
    float dv = 0.f;                // dist value for this thread's cell on diag k
    {
        int i = lo_l + tid;
        if (i <= hi_l) {           // k=0: only i=0
            int j = 0 - i, dji = j - i;
            if (dji >= -BW && dji <= BW - 1) dv = dist[(size_t)i * T + j];
        }
    }

    for (int k = 0; k < 2 * T - 1; ++k) {
        // prefetch dist for diag k+1 (independent of everything below)
        int lo2, hi2;
        dp_ranges(k + 1, lo2, hi2);
        float dnf = 0.f;
        {
            int i2 = lo2 + tid;
            if (k + 1 < 2 * T - 1 && i2 <= hi2) {
                int j2 = k + 1 - i2, dji2 = j2 - i2;
                if (dji2 >= -BW && dji2 <= BW - 1)
                    dnf = dist[(size_t)i2 * T + j2];
            }
        }

        int i = lo_l + tid;
        if (i <= hi_l) {           // band width <= 85 < 96: one cell per thread
            int j = k - i;
            int dji = j - i;
            bool inb = (dji >= -BW) && (dji <= BW - 1);
            float v = 0.0f;
            if (inb) {
                if (i == 0 && j == 0) {
                    v = dv;
                } else {
                    float up = prev1[i];       // (i-1, j)
                    float lf = prev1[i + 1];   // (i, j-1)
                    float dg = prev2[i];       // (i-1, j-1)
                    bool vu = (i > 0), vl = (j > 0), vd = vu && vl;
                    float m = -3.4e38f;
                    if (vd) m = fmaxf(m, -dg);
                    if (vu) m = fmaxf(m, -up);
                    if (vl) m = fmaxf(m, -lf);
                    float s = 0.f;
                    if (vd) s += expf(-dg - m);
                    if (vu) s += expf(-up - m);
                    if (vl) s += expf(-lf - m);
                    v = dv - m - logf(s);      // d + softmin (max-subtracted LSE)
                }
                dp[(size_t)i * T + j] = v;
            }
            cur[i + 1] = v;
        }
        __syncthreads();
        float* t0 = prev2; prev2 = prev1; prev1 = cur; cur = t0;
        dv = dnf;
        lo_l = lo2; hi_l = hi2;
    }
}

// ---------------------------------------------------------------------------
// Kernel 3: in-place row softmax of -DP (out-of-band treated as value 0).
// One CTA per (b, t1) row. Never reads out-of-band (poisoned) cells.
// ---------------------------------------------------------------------------
__global__ void softmax_kernel(float* __restrict__ path) {
    int row = blockIdx.x;                  // b*T + t1
    int t1 = row % T;
    float* p = path + (size_t)row * T;
    __shared__ float zsh[T];
    __shared__ float red[8];
    int tid = threadIdx.x;                 // 256
    int jlo = t1 - BW, jhi = t1 + BW - 1;

    float lm = -3.4e38f;
    for (int j = tid; j < T; j += 256) {
        float v = (j >= jlo && j <= jhi) ? p[j] : 0.0f;
        float z = -v;
        zsh[j] = z;
        lm = fmaxf(lm, z);
    }
    #pragma unroll
    for (int o = 16; o; o >>= 1) lm = fmaxf(lm, __shfl_xor_sync(0xFFFFFFFFu, lm, o));
    if ((tid & 31) == 0) red[tid >> 5] = lm;
    __syncthreads();
    float m = -3.4e38f;
    #pragma unroll
    for (int w = 0; w < 8; w++) m = fmaxf(m, red[w]);
    __syncthreads();

    float ls = 0.f;
    for (int j = tid; j < T; j += 256) {
        float e = expf(zsh[j] - m);
        zsh[j] = e;
        ls += e;
    }
    #pragma unroll
    for (int o = 16; o; o >>= 1) ls += __shfl_xor_sync(0xFFFFFFFFu, ls, o);
    if ((tid & 31) == 0) red[tid >> 5] = ls;
    __syncthreads();
    float s = 0.f;
    #pragma unroll
    for (int w = 0; w < 8; w++) s += red[w];
    float inv = 1.0f / s;
    for (int j = tid; j < T; j += 256) p[j] = zsh[j] * inv;
}

// ---------------------------------------------------------------------------
// Kernel 4: column sums. CTA per (b, 32-col strip); 8 warps split t; smem tree.
// Deterministic (fixed reduction order), 8x the parallelism of the old version.
// ---------------------------------------------------------------------------
__global__ void colsum_kernel(const float* __restrict__ path) {
    int b  = blockIdx.y;
    int s0 = blockIdx.x * 32;
    int tx = threadIdx.x & 31;
    int ty = threadIdx.x >> 5;             // 8 warps
    const float* p = path + (size_t)b * T * T + s0 + tx;
    float acc = 0.f;
    #pragma unroll 4
    for (int t = ty; t < T; t += 8) acc += p[(size_t)t * T];
    __shared__ float red[8][33];
    red[ty][tx] = acc;
    __syncthreads();
    if (ty == 0) {
        float s = 1e-10f;
        #pragma unroll
        for (int w = 0; w < 8; w++) s += red[w][tx];
        g_colsum[b * T + s0 + tx] = s;
    }
}

// ---------------------------------------------------------------------------
// Kernel 5: aligned[b,s,d] = (sum_t path[b,t,s] * x[b,t,d]) / colsum[b,s]
// Batched fp32 GEMM, 64x128x32 tiles, 4x8 blocking, cp.async double buffer.
// B fragments split as [tx*4] and [64+tx*4]: conflict-free LDS.128 phases.
// ---------------------------------------------------------------------------
#define BM 64
#define BN 128
#define BK 32
#define NT (T / BK)    // 10

__global__ void __launch_bounds__(256)
aligned_gemm(const float* __restrict__ path, const float* __restrict__ x,
             float* __restrict__ out) {
    int b  = blockIdx.z;
    int s0 = blockIdx.y * BM;
    int d0 = blockIdx.x * BN;
    const float* P = path + (size_t)b * T * T;
    const float* X = x    + (size_t)b * T * D;
    float*       O = out  + (size_t)b * T * D;

    __shared__ float As[2][BK][BM];   // 16KB
    __shared__ float Bs[2][BK][BN];   // 32KB

    int tid = threadIdx.x;            // 256
    int tx = tid & 15;
    int ty = tid >> 4;
    float acc[4][8] = {};

    // async tile loader
    auto load_tile = [&](int t0, int bf) {
        #pragma unroll
        for (int v = 0; v < 2; v++) {
            int idx = tid + v * 256;           // As: 512 float4
            int t = idx >> 4, c4 = idx & 15;
            cp16(&As[bf][t][c4 * 4], P + (size_t)(t0 + t) * T + s0 + c4 * 4);
        }
        #pragma unroll
        for (int v = 0; v < 4; v++) {
            int idx = tid + v * 256;           // Bs: 1024 float4
            int t = idx >> 5, c4 = idx & 31;
            cp16(&Bs[bf][t][c4 * 4], X + (size_t)(t0 + t) * D + d0 + c4 * 4);
        }
    };

    load_tile(0, 0);
    CP_COMMIT();

    for (int kt = 0; kt < NT; ++kt) {
        int bf = kt & 1;
        if (kt + 1 < NT) {
            load_tile((kt + 1) * BK, (kt + 1) & 1);
            CP_COMMIT();
            CP_WAIT(1);      // tile kt complete; tile kt+1 in flight
        } else {
            CP_WAIT(0);
        }
        __syncthreads();

        #pragma unroll
        for (int t = 0; t < BK; ++t) {
            float4 a  = *(const float4*)&As[bf][t][ty * 4];
            float4 b0 = *(const float4*)&Bs[bf][t][tx * 4];
            float4 b1 = *(const float4*)&Bs[bf][t][64 + tx * 4];
            float av[4] = {a.x, a.y, a.z, a.w};
            float bv[8] = {b0.x, b0.y, b0.z, b0.w, b1.x, b1.y, b1.z, b1.w};
            #pragma unroll
            for (int r = 0; r < 4; ++r)
                #pragma unroll
                for (int c = 0; c < 8; ++c)
                    acc[r][c] = fmaf(av[r], bv[c], acc[r][c]);
        }
        __syncthreads();
    }

    #pragma unroll
    for (int r = 0; r < 4; ++r) {
        int s = s0 + ty * 4 + r;
        float inv = 1.0f / g_colsum[b * T + s];
        float4 o0, o1;
        o0.x = acc[r][0]*inv; o0.y = acc[r][1]*inv; o0.z = acc[r][2]*inv; o0.w = acc[r][3]*inv;
        o1.x = acc[r][4]*inv; o1.y = acc[r][5]*inv; o1.z = acc[r][6]*inv; o1.w = acc[r][7]*inv;
        *(float4*)(O + (size_t)s * D + d0 + tx * 4)      = o0;
        *(float4*)(O + (size_t)s * D + d0 + 64 + tx * 4) = o1;
    }
}

// ---------------------------------------------------------------------------
extern "C" void kernel_launch(void* const* d_in, const int* in_sizes, int n_in,
                              void* d_out, int out_size) {
    const float* x   = (const float*)d_in[0];
    const float* y   = (const float*)d_in[1];
    const float* W   = (const float*)d_in[2];
    const float* bb  = (const float*)d_in[3];
    const float* wsc = (const float*)d_in[4];
    const float* wsh = (const float*)d_in[5];

    float* aligned = (float*)d_out;                        // [B,T,D]
    float* path    = (float*)d_out + ALIGNED_ELEMS;        // [B,T,T]

    // 1. projection (+ row norms)
    proj_kernel<<<NROWS / PJ_ROWS, PJ_THREADS>>>(x, y, W, bb, wsc, wsh);

    // 2a. banded distance matrix
    dim3 dg(T / DI, BATCH);
    dist_kernel<<<dg, 256>>>();

    // 2b. wavefront DP
    dp_kernel<<<BATCH, DP_THREADS>>>(path);

    // 3. row softmax (in place)
    softmax_kernel<<<BATCH * T, 256>>>(path);

    // 4. column sums
    dim3 cg(T / 32, BATCH);
    colsum_kernel<<<cg, 256>>>(path);

    // 5. aligned output
    dim3 g(D / BN, T / BM, BATCH);
    aligned_gemm<<<g, 256>>>(path, x, aligned);
}

// round 10
// speedup vs baseline: 1.1834x; 1.0145x over previous
#include <cuda_runtime.h>
#include <cuda_bf16.h>
#include <math.h>
#include <stdint.h>

// Problem constants
#define BATCH 64
#define T 320
#define D 768
#define WD 32
#define BW 81           // max(T1,T2)//4 + 1

#define NROWS (2*BATCH*T)          // 40960 projected rows (x then y)
#define ALIGNED_ELEMS ((size_t)BATCH*T*D)

// Scratch (static device globals: allocation-free)
__device__ float g_xw[BATCH*T*WD];
__device__ float g_yw[BATCH*T*WD];
__device__ float g_nx[BATCH*T];
__device__ float g_ny[BATCH*T];
__device__ float g_colsum[BATCH*T];
__device__ float g_dist[(size_t)BATCH*T*T];   // banded distance matrix (L2-resident)

// ---------------------------------------------------------------------------
// cp.async helpers
// ---------------------------------------------------------------------------
__device__ __forceinline__ void cp16(void* s, const void* g) {
    unsigned sa = (unsigned)__cvta_generic_to_shared(s);
    asm volatile("cp.async.cg.shared.global [%0], [%1], 16;" :: "r"(sa), "l"(g));
}
#define CP_COMMIT() asm volatile("cp.async.commit_group;" ::: "memory")
#define CP_WAIT(n)  asm volatile("cp.async.wait_group %0;" :: "n"(n) : "memory")

// tf32 helpers
__device__ __forceinline__ uint32_t f2tf32(float v) {
    uint32_t r; asm("cvt.rna.tf32.f32 %0, %1;" : "=r"(r) : "f"(v)); return r;
}
__device__ __forceinline__ void mma_tf32(float d[4],
                                         uint32_t a0, uint32_t a1, uint32_t a2, uint32_t a3,
                                         uint32_t b0, uint32_t b1) {
    asm volatile("mma.sync.aligned.m16n8k8.row.col.f32.tf32.tf32.f32 "
                 "{%0,%1,%2,%3}, {%4,%5,%6,%7}, {%8,%9}, {%0,%1,%2,%3};"
                 : "+f"(d[0]), "+f"(d[1]), "+f"(d[2]), "+f"(d[3])
                 : "r"(a0), "r"(a1), "r"(a2), "r"(a3), "r"(b0), "r"(b1));
}

// ---------------------------------------------------------------------------
// Kernel 1: projection as a tiled GEMM + row norms.
// ---------------------------------------------------------------------------
#define PJ_ROWS 64
#define PJ_KC 64
#define PJ_THREADS 256
#define WS_STRIDE 33

__global__ void proj_kernel(const float* __restrict__ x, const float* __restrict__ y,
                            const float* __restrict__ W, const float* __restrict__ bias,
                            const float* __restrict__ wsc, const float* __restrict__ wsh) {
    __shared__ float xs[PJ_ROWS][PJ_KC];        // [row][k]
    __shared__ float ws[PJ_KC][WS_STRIDE];      // [k][wd] padded

    int tid = threadIdx.x;
    int wd   = tid & 31;
    int rgrp = tid >> 5;

    int row0 = blockIdx.x * PJ_ROWS;
    bool is_x = (row0 < BATCH*T);
    const float* src = is_x ? (x + (size_t)row0 * D)
                            : (y + (size_t)(row0 - BATCH*T) * D);

    float acc[8];
    #pragma unroll
    for (int r = 0; r < 8; r++) acc[r] = 0.f;

    for (int k0 = 0; k0 < D; k0 += PJ_KC) {
        #pragma unroll
        for (int v = 0; v < 4; v++) {
            int idx = tid + v * PJ_THREADS;
            int r = idx >> 4;
            int c4 = idx & 15;
            float4 val = *(const float4*)(src + (size_t)r * D + k0 + c4 * 4);
            *(float4*)&xs[r][c4 * 4] = val;
        }
        #pragma unroll
        for (int v = 0; v < 8; v++) {
            int idx = tid + v * PJ_THREADS;
            int w = idx >> 6;
            int kc = idx & 63;
            ws[kc][w] = W[(size_t)w * D + k0 + kc];
        }
        __syncthreads();
        #pragma unroll
        for (int kc = 0; kc < PJ_KC; kc++) {
            float wv = ws[kc][wd];
            #pragma unroll
            for (int r = 0; r < 8; r++)
                acc[r] = fmaf(xs[rgrp * 8 + r][kc], wv, acc[r]);
        }
        __syncthreads();
    }

    float bv = bias[wd], sc = wsc[wd], sh = wsh[wd];
    float* dst = is_x ? (g_xw + (size_t)row0 * WD)
                      : (g_yw + (size_t)(row0 - BATCH*T) * WD);
    float* ndst = is_x ? (g_nx + row0) : (g_ny + (row0 - BATCH*T));
    #pragma unroll
    for (int r = 0; r < 8; r++) {
        int row = rgrp * 8 + r;
        float v = fmaf(acc[r] + bv, sc, sh);
        dst[(size_t)row * WD + wd] = v;
        float sq = v * v;
        #pragma unroll
        for (int o = 16; o; o >>= 1) sq += __shfl_xor_sync(0xFFFFFFFFu, sq, o);
        if (wd == 0) ndst[row] = sq;
    }
}

// ---------------------------------------------------------------------------
// Kernel 2a: banded distance matrix.
// ---------------------------------------------------------------------------
#define DI 16

__global__ void dist_kernel() {
    int b  = blockIdx.y;
    int i0 = blockIdx.x * DI;
    __shared__ float xs[DI][33];
    __shared__ float ys[DI][33];
    __shared__ float nxs[DI], nys[DI];

    int tid = threadIdx.x;     // 256
    const float* gx = g_xw + ((size_t)b * T + i0) * WD;
    for (int idx = tid; idx < DI * WD; idx += 256)
        xs[idx >> 5][idx & 31] = gx[idx];
    if (tid < DI) nxs[tid] = g_nx[b * T + i0 + tid];

    int jlo = max(0, i0 - BW);
    int jhi = min(T - 1, i0 + DI - 1 + BW - 1);
    int il = tid >> 4, jl = tid & 15;
    float* drow = g_dist + ((size_t)b * T + i0 + il) * T;

    for (int j0 = jlo; j0 <= jhi; j0 += DI) {
        __syncthreads();
        for (int idx = tid; idx < DI * WD; idx += 256) {
            int r = idx >> 5;
            if (j0 + r < T)
                ys[r][idx & 31] = g_yw[((size_t)b * T + j0 + r) * WD + (idx & 31)];
        }
        if (tid < DI && j0 + tid < T) nys[tid] = g_ny[b * T + j0 + tid];
        __syncthreads();

        int i = i0 + il, j = j0 + jl;
        if (j < T && j >= i - BW && j <= i + BW - 1) {
            float a0 = 0.f, a1 = 0.f, a2 = 0.f, a3 = 0.f;
            #pragma unroll
            for (int c = 0; c < WD; c += 4) {
                a0 = fmaf(xs[il][c+0], ys[jl][c+0], a0);
                a1 = fmaf(xs[il][c+1], ys[jl][c+1], a1);
                a2 = fmaf(xs[il][c+2], ys[jl][c+2], a2);
                a3 = fmaf(xs[il][c+3], ys[jl][c+3], a3);
            }
            float dot = (a0 + a1) + (a2 + a3);
            drow[j] = nxs[il] + nys[jl] - 2.0f * dot;
        }
    }
}

// ---------------------------------------------------------------------------
// Kernel 2b: banded soft-DTW DP wavefront, one CTA per batch (verified R4).
// ---------------------------------------------------------------------------
#define DP_THREADS 96
#define BUFSZ 324

__device__ __forceinline__ void dp_ranges(int k, int& lo_l, int& hi_l) {
    int lo_full = max(0, k - (T - 1));
    int hi_full = min(T - 1, k);
    int lo_b = (k >= BW - 2) ? ((k - (BW - 2)) >> 1) : 0;
    if (lo_b < lo_full) lo_b = lo_full;
    int hi_b = (k + BW) >> 1;
    if (hi_b > hi_full) hi_b = hi_full;
    lo_l = max(lo_full, lo_b - 2);
    hi_l = min(hi_full, hi_b + 2);
}

__global__ void dp_kernel(float* __restrict__ path) {
    int b = blockIdx.x;
    __shared__ float buf[3 * BUFSZ];
    int tid = threadIdx.x;
    for (int idx = tid; idx < 3 * BUFSZ; idx += DP_THREADS) buf[idx] = 0.f;
    __syncthreads();

    float* prev2 = buf;
    float* prev1 = buf + BUFSZ;
    float* cur   = buf + 2 * BUFSZ;
    float* dp = path + (size_t)b * T * T;
    const float* dist = g_dist + (size_t)b * T * T;

    int lo_l, hi_l;
    dp_ranges(0, lo_l, hi_l);
    float dv = 0.f;
    {
        int i = lo_l + tid;
        if (i <= hi_l) {
            int j = 0 - i, dji = j - i;
            if (dji >= -BW && dji <= BW - 1) dv = dist[(size_t)i * T + j];
        }
    }

    for (int k = 0; k < 2 * T - 1; ++k) {
        int lo2, hi2;
        dp_ranges(k + 1, lo2, hi2);
        float dnf = 0.f;
        {
            int i2 = lo2 + tid;
            if (k + 1 < 2 * T - 1 && i2 <= hi2) {
                int j2 = k + 1 - i2, dji2 = j2 - i2;
                if (dji2 >= -BW && dji2 <= BW - 1)
                    dnf = dist[(size_t)i2 * T + j2];
            }
        }

        int i = lo_l + tid;
        if (i <= hi_l) {
            int j = k - i;
            int dji = j - i;
            bool inb = (dji >= -BW) && (dji <= BW - 1);
            float v = 0.0f;
            if (inb) {
                if (i == 0 && j == 0) {
                    v = dv;
                } else {
                    float up = prev1[i];
                    float lf = prev1[i + 1];
                    float dg = prev2[i];
                    bool vu = (i > 0), vl = (j > 0), vd = vu && vl;
                    float m = -3.4e38f;
                    if (vd) m = fmaxf(m, -dg);
                    if (vu) m = fmaxf(m, -up);
                    if (vl) m = fmaxf(m, -lf);
                    float s = 0.f;
                    if (vd) s += expf(-dg - m);
                    if (vu) s += expf(-up - m);
                    if (vl) s += expf(-lf - m);
                    v = dv - m - logf(s);
                }
                dp[(size_t)i * T + j] = v;
            }
            cur[i + 1] = v;
        }
        __syncthreads();
        float* t0 = prev2; prev2 = prev1; prev1 = cur; cur = t0;
        dv = dnf;
        lo_l = lo2; hi_l = hi2;
    }
}

// ---------------------------------------------------------------------------
// Kernel 3: in-place row softmax of -DP (out-of-band treated as value 0).
// ---------------------------------------------------------------------------
__global__ void softmax_kernel(float* __restrict__ path) {
    int row = blockIdx.x;
    int t1 = row % T;
    float* p = path + (size_t)row * T;
    __shared__ float zsh[T];
    __shared__ float red[8];
    int tid = threadIdx.x;
    int jlo = t1 - BW, jhi = t1 + BW - 1;

    float lm = -3.4e38f;
    for (int j = tid; j < T; j += 256) {
        float v = (j >= jlo && j <= jhi) ? p[j] : 0.0f;
        float z = -v;
        zsh[j] = z;
        lm = fmaxf(lm, z);
    }
    #pragma unroll
    for (int o = 16; o; o >>= 1) lm = fmaxf(lm, __shfl_xor_sync(0xFFFFFFFFu, lm, o));
    if ((tid & 31) == 0) red[tid >> 5] = lm;
    __syncthreads();
    float m = -3.4e38f;
    #pragma unroll
    for (int w = 0; w < 8; w++) m = fmaxf(m, red[w]);
    __syncthreads();

    float ls = 0.f;
    for (int j = tid; j < T; j += 256) {
        float e = expf(zsh[j] - m);
        zsh[j] = e;
        ls += e;
    }
    #pragma unroll
    for (int o = 16; o; o >>= 1) ls += __shfl_xor_sync(0xFFFFFFFFu, ls, o);
    if ((tid & 31) == 0) red[tid >> 5] = ls;
    __syncthreads();
    float s = 0.f;
    #pragma unroll
    for (int w = 0; w < 8; w++) s += red[w];
    float inv = 1.0f / s;
    for (int j = tid; j < T; j += 256) p[j] = zsh[j] * inv;
}

// ---------------------------------------------------------------------------
// Kernel 4: column sums (deterministic 2D reduce).
// ---------------------------------------------------------------------------
__global__ void colsum_kernel(const float* __restrict__ path) {
    int b  = blockIdx.y;
    int s0 = blockIdx.x * 32;
    int tx = threadIdx.x & 31;
    int ty = threadIdx.x >> 5;
    const float* p = path + (size_t)b * T * T + s0 + tx;
    float acc = 0.f;
    #pragma unroll 4
    for (int t = ty; t < T; t += 8) acc += p[(size_t)t * T];
    __shared__ float red[8][33];
    red[ty][tx] = acc;
    __syncthreads();
    if (ty == 0) {
        float s = 1e-10f;
        #pragma unroll
        for (int w = 0; w < 8; w++) s += red[w][tx];
        g_colsum[b * T + s0 + tx] = s;
    }
}

// ---------------------------------------------------------------------------
// Kernel 5: aligned[b,s,d] = (sum_t P[t,s] * X[t,d]) / colsum[b,s]
// Tensor-core GEMM: mma.sync.m16n8k8.tf32 with 3xTF32 (hi/lo) for fp32-class
// accuracy. CTA 64(s) x 128(d), 8 warps (2m x 4n), warp tile 32x32.
// cp.async double-buffered tiles, padded smem strides.
// ---------------------------------------------------------------------------
#define BM 64
#define BN 128
#define BK 16
#define NT (T / BK)    // 20
#define SA 68          // BM+4 pad
#define SB 132         // BN+4 pad

__global__ void __launch_bounds__(256)
aligned_gemm(const float* __restrict__ path, const float* __restrict__ x,
             float* __restrict__ out) {
    int b  = blockIdx.z;
    int s0 = blockIdx.y * BM;
    int d0 = blockIdx.x * BN;
    const float* P = path + (size_t)b * T * T;
    const float* X = x    + (size_t)b * T * D;
    float*       O = out  + (size_t)b * T * D;

    __shared__ float As[2][BK][SA];   // [t][s]  8.7KB
    __shared__ float Bs[2][BK][SB];   // [t][d] 16.9KB

    int tid  = threadIdx.x;           // 256
    int lane = tid & 31;
    int wid  = tid >> 5;              // 8 warps
    int wm   = wid & 1;               // 2 m-warps
    int wn   = wid >> 1;              // 4 n-warps
    int g  = lane >> 2;               // group row 0..7
    int c  = lane & 3;                // thread-in-group 0..3

    float acc[2][4][4];
    #pragma unroll
    for (int mi = 0; mi < 2; mi++)
        #pragma unroll
        for (int ni = 0; ni < 4; ni++)
            #pragma unroll
            for (int r = 0; r < 4; r++) acc[mi][ni][r] = 0.f;

    auto load_tile = [&](int t0, int bf) {
        // As: 16 rows x 16 float4 = 256 -> 1 per thread
        {
            int t = tid >> 4, c4 = tid & 15;
            cp16(&As[bf][t][c4 * 4], P + (size_t)(t0 + t) * T + s0 + c4 * 4);
        }
        // Bs: 16 rows x 32 float4 = 512 -> 2 per thread
        #pragma unroll
        for (int v = 0; v < 2; v++) {
            int idx = tid + v * 256;
            int t = idx >> 5, c4 = idx & 31;
            cp16(&Bs[bf][t][c4 * 4], X + (size_t)(t0 + t) * D + d0 + c4 * 4);
        }
    };

    load_tile(0, 0);
    CP_COMMIT();

    for (int kt = 0; kt < NT; ++kt) {
        int bf = kt & 1;
        if (kt + 1 < NT) {
            load_tile((kt + 1) * BK, (kt + 1) & 1);
            CP_COMMIT();
            CP_WAIT(1);
        } else {
            CP_WAIT(0);
        }
        __syncthreads();

        #pragma unroll
        for (int kk = 0; kk < BK; kk += 8) {
            // A fp32 fragments (m16k8, row-major): rows = s, cols = t
            float af[2][4];
            #pragma unroll
            for (int mi = 0; mi < 2; mi++) {
                int ms = wm * 32 + mi * 16;
                af[mi][0] = As[bf][kk + c    ][ms + g    ];
                af[mi][1] = As[bf][kk + c    ][ms + g + 8];
                af[mi][2] = As[bf][kk + c + 4][ms + g    ];
                af[mi][3] = As[bf][kk + c + 4][ms + g + 8];
            }
            // B fp32 fragments (k8n8, col-major): rows = t, cols = d
            float bfr[4][2];
            #pragma unroll
            for (int ni = 0; ni < 4; ni++) {
                int ns = wn * 32 + ni * 8;
                bfr[ni][0] = Bs[bf][kk + c    ][ns + g];
                bfr[ni][1] = Bs[bf][kk + c + 4][ns + g];
            }
            // hi/lo tf32 split
            uint32_t ah[2][4], al[2][4], bh[4][2], bl[4][2];
            #pragma unroll
            for (int mi = 0; mi < 2; mi++)
                #pragma unroll
                for (int r = 0; r < 4; r++) {
                    uint32_t h = f2tf32(af[mi][r]);
                    ah[mi][r] = h;
                    al[mi][r] = f2tf32(af[mi][r] - __uint_as_float(h));
                }
            #pragma unroll
            for (int ni = 0; ni < 4; ni++)
                #pragma unroll
                for (int r = 0; r < 2; r++) {
                    uint32_t h = f2tf32(bfr[ni][r]);
                    bh[ni][r] = h;
                    bl[ni][r] = f2tf32(bfr[ni][r] - __uint_as_float(h));
                }
            // 3xTF32: hi*hi + hi*lo + lo*hi
            #pragma unroll
            for (int mi = 0; mi < 2; mi++)
                #pragma unroll
                for (int ni = 0; ni < 4; ni++) {
                    mma_tf32(acc[mi][ni], ah[mi][0], ah[mi][1], ah[mi][2], ah[mi][3],
                             bh[ni][0], bh[ni][1]);
                    mma_tf32(acc[mi][ni], ah[mi][0], ah[mi][1], ah[mi][2], ah[mi][3],
                             bl[ni][0], bl[ni][1]);
                    mma_tf32(acc[mi][ni], al[mi][0], al[mi][1], al[mi][2], al[mi][3],
                             bh[ni][0], bh[ni][1]);
                }
        }
        __syncthreads();
    }

    // epilogue: scale by 1/colsum[s], write float2 pairs
    int c2 = c * 2;
    #pragma unroll
    for (int mi = 0; mi < 2; mi++) {
        #pragma unroll
        for (int h = 0; h < 2; h++) {
            int s = s0 + wm * 32 + mi * 16 + g + 8 * h;
            float inv = 1.0f / g_colsum[b * T + s];
            #pragma unroll
            for (int ni = 0; ni < 4; ni++) {
                int d = d0 + wn * 32 + ni * 8 + c2;
                float2 o;
                o.x = acc[mi][ni][2 * h]     * inv;
                o.y = acc[mi][ni][2 * h + 1] * inv;
                *(float2*)(O + (size_t)s * D + d) = o;
            }
        }
    }
}

// ---------------------------------------------------------------------------
extern "C" void kernel_launch(void* const* d_in, const int* in_sizes, int n_in,
                              void* d_out, int out_size) {
    const float* x   = (const float*)d_in[0];
    const float* y   = (const float*)d_in[1];
    const float* W   = (const float*)d_in[2];
    const float* bb  = (const float*)d_in[3];
    const float* wsc = (const float*)d_in[4];
    const float* wsh = (const float*)d_in[5];

    float* aligned = (float*)d_out;                        // [B,T,D]
    float* path    = (float*)d_out + ALIGNED_ELEMS;        // [B,T,T]

    // 1. projection (+ row norms)
    proj_kernel<<<NROWS / PJ_ROWS, PJ_THREADS>>>(x, y, W, bb, wsc, wsh);

    // 2a. banded distance matrix
    dim3 dg(T / DI, BATCH);
    dist_kernel<<<dg, 256>>>();

    // 2b. wavefront DP
    dp_kernel<<<BATCH, DP_THREADS>>>(path);

    // 3. row softmax (in place)
    softmax_kernel<<<BATCH * T, 256>>>(path);

    // 4. column sums
    dim3 cg(T / 32, BATCH);
    colsum_kernel<<<cg, 256>>>(path);

    // 5. aligned output (tensor-core 3xTF32)
    dim3 g(D / BN, T / BM, BATCH);
    aligned_gemm<<<g, 256>>>(path, x, aligned);
}